// round 8
// baseline (speedup 1.0000x reference)
#include <cuda_runtime.h>
#include <cstdint>

// ---------------------------------------------------------------------------
// FTLayer fused kernel, fp32 with packed f32x2 FMA + 2D register tiling +
// pre-duplicated (w,w) weight pairs to kill per-k pack MOVs.  sm_103a.
// Shapes: B=4, A=512, N=128, F=256.  neighbors = int32 (JAX x64 disabled).
// Output: (B,A,128,256) f32
// ---------------------------------------------------------------------------

#define Bv 4
#define Av 512
#define Nv 128
#define Fv 256
#define ROWS_TOTAL (Bv * Av * Nv)   // 262144 pair-rows
#define TILE 64                     // rows per block
#define HTS 68                      // padded stride for transposed h/y tile (16B aligned)

// Scratch: facts = x @ in2f_w + in2f_b   (B*A, 256) = 2 MB, L2-resident
__device__ float g_facts[Bv * Av * Fv];
// Duplicated weights: row k holds [w(k,0),w(k,0),w(k,1),w(k,1),...] (512 f/row)
__device__ float g_fw2d[Fv * Fv * 2];   // 512 KB
__device__ float g_f2wd[Fv * Fv * 2];   // 512 KB

// ---- packed f32x2 helpers --------------------------------------------------
__device__ __forceinline__ unsigned long long pack2(float lo, float hi) {
    unsigned long long d;
    asm("mov.b64 %0, {%1, %2};" : "=l"(d) : "f"(lo), "f"(hi));
    return d;
}
__device__ __forceinline__ float2 unpack2(unsigned long long v) {
    float2 r;
    asm("mov.b64 {%0, %1}, %2;" : "=f"(r.x), "=f"(r.y) : "l"(v));
    return r;
}
__device__ __forceinline__ unsigned long long fma2(unsigned long long a,
                                                   unsigned long long b,
                                                   unsigned long long c) {
    unsigned long long d;
    asm("fma.rn.f32x2 %0, %1, %2, %3;" : "=l"(d) : "l"(a), "l"(b), "l"(c));
    return d;
}

// shifted softplus: softplus(v) - ln(2), stable form matching jax.nn.softplus
__device__ __forceinline__ float sspf(float v) {
    float a = fabsf(v);
    return fmaxf(v, 0.0f) + log1pf(__expf(-a)) - 0.6931471824645996f;
}

// ---------------------------------------------------------------------------
// Kernel 0: duplicate weights into (w,w) pair layout. 65536 threads.
// ---------------------------------------------------------------------------
__global__ __launch_bounds__(256) void dup_weights_kernel(
    const float* __restrict__ fw2, const float* __restrict__ f2w) {
    const int i = blockIdx.x * 256 + threadIdx.x;   // 0..65535
    const int k = i >> 8, c = i & 255;
    const float a = fw2[i];
    const float b = f2w[i];
    const int o = k * 512 + 2 * c;
    g_fw2d[o] = a; g_fw2d[o + 1] = a;
    g_f2wd[o] = b; g_f2wd[o + 1] = b;
}

// ---------------------------------------------------------------------------
// Kernel 1: facts = x @ in2f_w + in2f_b.  16 rows/block, 128 blocks, 256 thr.
// ---------------------------------------------------------------------------
__global__ __launch_bounds__(256) void facts_kernel(
    const float* __restrict__ x, const float* __restrict__ w,
    const float* __restrict__ b) {
    __shared__ float xs[16][Fv];
    const int t = threadIdx.x;
    const int r0 = blockIdx.x * 16;
    #pragma unroll
    for (int m = 0; m < 16; m++) xs[m][t] = x[(r0 + m) * Fv + t];
    __syncthreads();

    float acc[16];
    const float bias = b[t];
    #pragma unroll
    for (int m = 0; m < 16; m++) acc[m] = bias;

    for (int k4 = 0; k4 < Fv / 4; k4++) {
        const float w0 = w[(4 * k4 + 0) * Fv + t];
        const float w1 = w[(4 * k4 + 1) * Fv + t];
        const float w2 = w[(4 * k4 + 2) * Fv + t];
        const float w3 = w[(4 * k4 + 3) * Fv + t];
        #pragma unroll
        for (int m = 0; m < 16; m++) {
            float4 xv = *reinterpret_cast<const float4*>(&xs[m][4 * k4]);
            acc[m] = fmaf(xv.x, w0, acc[m]);
            acc[m] = fmaf(xv.y, w1, acc[m]);
            acc[m] = fmaf(xv.z, w2, acc[m]);
            acc[m] = fmaf(xv.w, w3, acc[m]);
        }
    }
    #pragma unroll
    for (int m = 0; m < 16; m++) g_facts[(r0 + m) * Fv + t] = acc[m];
}

// ---------------------------------------------------------------------------
// Kernel 2: fused main kernel. Block = 64 pair-rows x 256 cols, 256 threads.
// Thread tile: 16 rows x 4 cols (rg = tid>>6, cg = tid&63).
// Per k: 4 LDS.128 (broadcast h rows) + 2 LDG.128 (dup weights) + 32 FFMA2.
// ---------------------------------------------------------------------------
__global__ __launch_bounds__(256, 2) void ftlayer_main_kernel(
    const float* __restrict__ r_ij,
    const int* __restrict__ neighbors,
    const float* __restrict__ fw1, const float* __restrict__ fb1,
    const float* __restrict__ fb2,
    const float* __restrict__ f2b,
    float* __restrict__ out) {
    extern __shared__ float sm[];
    float* hT  = sm;                          // [256][HTS]  transposed h, later y
    float* r_s = sm + Fv * HTS;               // [TILE]
    int*   rjs = reinterpret_cast<int*>(r_s + TILE);  // [TILE]

    const int t   = threadIdx.x;
    const int rg  = t >> 6;                   // 0..3   row group
    const int cg  = t & 63;                   // 0..63  col group
    const int r0t = rg * 16;                  // thread's first row in tile
    const int c0  = cg * 4;                   // thread's first col

    const int row0 = blockIdx.x * TILE;       // global pair-row base
    const int ba = row0 >> 7;                 // (b*A + a), since N=128
    const int bbase = (ba >> 9) << 9;         // b*A

    if (t < TILE) {
        int j = neighbors[row0 + t];
        j = min(max(j, 0), Av - 1);           // defensive clamp
        rjs[t] = bbase + j;
        r_s[t] = r_ij[row0 + t];
    }
    __syncthreads();

    // h transposed: thread t handles k=t for all 64 rows
    {
        const float w1v = fw1[t];
        const float b1v = fb1[t];
        float* hrow = hT + t * HTS;
        #pragma unroll 4
        for (int m = 0; m < TILE; m++)
            hrow[m] = sspf(fmaf(r_s[m], w1v, b1v));
    }
    __syncthreads();

    unsigned long long acc[32];               // [c][q]: 4 cols x 8 row-pairs

    // ---- GEMM1: W = h @ fw2 + fb2 (thread computes 16x4 tile) ----
    {
        const float4 b4 = *reinterpret_cast<const float4*>(fb2 + c0);
        const float bb[4] = {b4.x, b4.y, b4.z, b4.w};
        #pragma unroll
        for (int c = 0; c < 4; c++) {
            const unsigned long long bp = pack2(bb[c], bb[c]);
            #pragma unroll
            for (int q = 0; q < 8; q++) acc[c * 8 + q] = bp;
        }
    }
    {
        // duplicated weight pairs for cols c0..c0+3: 32 B/row, row stride 128 u2
        const ulonglong2* wp =
            reinterpret_cast<const ulonglong2*>(g_fw2d + 2 * c0);
        const float* hbase = hT + r0t;
        #pragma unroll 2
        for (int k = 0; k < Fv; k++) {
            const ulonglong2 wA = wp[k * 128];
            const ulonglong2 wB = wp[k * 128 + 1];
            const ulonglong2* hp =
                reinterpret_cast<const ulonglong2*>(hbase + k * HTS);
            ulonglong2 ha = hp[0], hb = hp[1], hc = hp[2], hd = hp[3];
            const unsigned long long h[8] = {ha.x, ha.y, hb.x, hb.y,
                                             hc.x, hc.y, hd.x, hd.y};
            const unsigned long long wd[4] = {wA.x, wA.y, wB.x, wB.y};
            #pragma unroll
            for (int c = 0; c < 4; c++) {
                #pragma unroll
                for (int q = 0; q < 8; q++)
                    acc[c * 8 + q] = fma2(h[q], wd[c], acc[c * 8 + q]);
            }
        }
    }

    // ---- epilogue 1: y = xi * W * xj ----
    {
        const float4 xi4 = *reinterpret_cast<const float4*>(g_facts + ba * Fv + c0);
        const float xiv[4] = {xi4.x, xi4.y, xi4.z, xi4.w};
        #pragma unroll
        for (int q = 0; q < 8; q++) {
            const int ra = r0t + 2 * q, rb = ra + 1;
            const float4 xa = *reinterpret_cast<const float4*>(g_facts + rjs[ra] * Fv + c0);
            const float4 xb = *reinterpret_cast<const float4*>(g_facts + rjs[rb] * Fv + c0);
            const float xav[4] = {xa.x, xa.y, xa.z, xa.w};
            const float xbv[4] = {xb.x, xb.y, xb.z, xb.w};
            #pragma unroll
            for (int c = 0; c < 4; c++) {
                float2 s = unpack2(acc[c * 8 + q]);
                acc[c * 8 + q] = pack2(xiv[c] * s.x * xav[c],
                                       xiv[c] * s.y * xbv[c]);
            }
        }
    }
    __syncthreads();   // all reads of hT (GEMM1) done
    // write y transposed: yT[col][row]
    {
        #pragma unroll
        for (int c = 0; c < 4; c++) {
            unsigned long long* yrow =
                reinterpret_cast<unsigned long long*>(hT + (c0 + c) * HTS + r0t);
            #pragma unroll
            for (int q = 0; q < 8; q++) yrow[q] = acc[c * 8 + q];
        }
    }
    __syncthreads();

    // ---- GEMM2: out = ssp(y @ f2out_w + f2out_b) ----
    {
        const float4 b4 = *reinterpret_cast<const float4*>(f2b + c0);
        const float bb[4] = {b4.x, b4.y, b4.z, b4.w};
        #pragma unroll
        for (int c = 0; c < 4; c++) {
            const unsigned long long bp = pack2(bb[c], bb[c]);
            #pragma unroll
            for (int q = 0; q < 8; q++) acc[c * 8 + q] = bp;
        }
    }
    {
        const ulonglong2* wp =
            reinterpret_cast<const ulonglong2*>(g_f2wd + 2 * c0);
        const float* ybase = hT + r0t;
        #pragma unroll 2
        for (int k = 0; k < Fv; k++) {
            const ulonglong2 wA = wp[k * 128];
            const ulonglong2 wB = wp[k * 128 + 1];
            const ulonglong2* yp =
                reinterpret_cast<const ulonglong2*>(ybase + k * HTS);
            ulonglong2 ya = yp[0], yb = yp[1], yc = yp[2], yd = yp[3];
            const unsigned long long y[8] = {ya.x, ya.y, yb.x, yb.y,
                                             yc.x, yc.y, yd.x, yd.y};
            const unsigned long long wd[4] = {wA.x, wA.y, wB.x, wB.y};
            #pragma unroll
            for (int c = 0; c < 4; c++) {
                #pragma unroll
                for (int q = 0; q < 8; q++)
                    acc[c * 8 + q] = fma2(y[q], wd[c], acc[c * 8 + q]);
            }
        }
    }

    // ---- epilogue 2: ssp + coalesced float4 stores ----
    {
        float* ob = out + (long long)row0 * Fv + c0;
        #pragma unroll
        for (int q = 0; q < 8; q++) {
            const int ra = r0t + 2 * q, rb = ra + 1;
            float2 s0 = unpack2(acc[0 * 8 + q]);
            float2 s1 = unpack2(acc[1 * 8 + q]);
            float2 s2 = unpack2(acc[2 * 8 + q]);
            float2 s3 = unpack2(acc[3 * 8 + q]);
            float4 oa  = make_float4(sspf(s0.x), sspf(s1.x), sspf(s2.x), sspf(s3.x));
            float4 ob4 = make_float4(sspf(s0.y), sspf(s1.y), sspf(s2.y), sspf(s3.y));
            *reinterpret_cast<float4*>(ob + (long long)ra * Fv) = oa;
            *reinterpret_cast<float4*>(ob + (long long)rb * Fv) = ob4;
        }
    }
}

// ---------------------------------------------------------------------------
extern "C" void kernel_launch(void* const* d_in, const int* in_sizes, int n_in,
                              void* d_out, int out_size) {
    const float* x      = (const float*)d_in[0];
    const float* r_ij   = (const float*)d_in[1];
    // d_in[2] pairwise_mask: unused by reference
    const float* in2f_w = (const float*)d_in[3];
    const float* in2f_b = (const float*)d_in[4];
    const float* f2w    = (const float*)d_in[5];
    const float* f2b    = (const float*)d_in[6];
    const float* fw1    = (const float*)d_in[7];
    const float* fb1    = (const float*)d_in[8];
    const float* fw2    = (const float*)d_in[9];
    const float* fb2    = (const float*)d_in[10];
    const int*   nbr    = (const int*)d_in[11];   // int32 (JAX x64 disabled)
    float* out = (float*)d_out;

    const size_t smem_bytes =
        (size_t)(Fv * HTS + TILE) * sizeof(float) + TILE * sizeof(int);

    cudaFuncSetAttribute(ftlayer_main_kernel,
                         cudaFuncAttributeMaxDynamicSharedMemorySize,
                         (int)smem_bytes);

    dup_weights_kernel<<<(Fv * Fv) / 256, 256>>>(fw2, f2w);
    facts_kernel<<<(Bv * Av) / 16, 256>>>(x, in2f_w, in2f_b);
    ftlayer_main_kernel<<<ROWS_TOTAL / TILE, 256, smem_bytes>>>(
        r_ij, nbr, fw1, fb1, fb2, f2b, out);
}

// round 10
// speedup vs baseline: 1.3362x; 1.3362x over previous
#include <cuda_runtime.h>
#include <cstdint>

// ---------------------------------------------------------------------------
// FTLayer fused kernel, fp32 / packed f32x2 FMA, 2D register tiling,
// double-buffered smem weight staging (kills weight-LDG long-scoreboard
// stalls).  sm_103a.  Shapes: B=4, A=512, N=128, F=256.
// neighbors = int32 (JAX x64 disabled).  Output: (B,A,128,256) f32
// ---------------------------------------------------------------------------

#define Bv 4
#define Av 512
#define Nv 128
#define Fv 256
#define ROWS_TOTAL (Bv * Av * Nv)   // 262144 pair-rows
#define TILE 64                     // rows per block
#define HTS 68                      // padded stride for transposed h/y tile
#define CHUNK 16                    // k-steps per staged weight chunk
#define CBF (CHUNK * Fv)            // floats per chunk = 4096 (16 KB)
#define NCHUNK (Fv / CHUNK)         // 16 chunks per GEMM

// Scratch: facts = x @ in2f_w + in2f_b   (B*A, 256) = 2 MB, L2-resident
__device__ float g_facts[Bv * Av * Fv];

// ---- packed f32x2 helpers --------------------------------------------------
__device__ __forceinline__ unsigned long long pack2(float lo, float hi) {
    unsigned long long d;
    asm("mov.b64 %0, {%1, %2};" : "=l"(d) : "f"(lo), "f"(hi));
    return d;
}
__device__ __forceinline__ float2 unpack2(unsigned long long v) {
    float2 r;
    asm("mov.b64 {%0, %1}, %2;" : "=f"(r.x), "=f"(r.y) : "l"(v));
    return r;
}
__device__ __forceinline__ unsigned long long fma2(unsigned long long a,
                                                   unsigned long long b,
                                                   unsigned long long c) {
    unsigned long long d;
    asm("fma.rn.f32x2 %0, %1, %2, %3;" : "=l"(d) : "l"(a), "l"(b), "l"(c));
    return d;
}

// shifted softplus: softplus(v) - ln(2), matches jax.nn.softplus - LOG2
__device__ __forceinline__ float sspf(float v) {
    float a = fabsf(v);
    return fmaxf(v, 0.0f) + log1pf(__expf(-a)) - 0.6931471824645996f;
}

// ---------------------------------------------------------------------------
// Kernel 1: facts = x @ in2f_w + in2f_b.  16 rows/block, 128 blocks, 256 thr.
// ---------------------------------------------------------------------------
__global__ __launch_bounds__(256) void facts_kernel(
    const float* __restrict__ x, const float* __restrict__ w,
    const float* __restrict__ b) {
    __shared__ float xs[16][Fv];
    const int t = threadIdx.x;
    const int r0 = blockIdx.x * 16;
    #pragma unroll
    for (int m = 0; m < 16; m++) xs[m][t] = x[(r0 + m) * Fv + t];
    __syncthreads();

    float acc[16];
    const float bias = b[t];
    #pragma unroll
    for (int m = 0; m < 16; m++) acc[m] = bias;

    for (int k4 = 0; k4 < Fv / 4; k4++) {
        const float w0 = w[(4 * k4 + 0) * Fv + t];
        const float w1 = w[(4 * k4 + 1) * Fv + t];
        const float w2 = w[(4 * k4 + 2) * Fv + t];
        const float w3 = w[(4 * k4 + 3) * Fv + t];
        #pragma unroll
        for (int m = 0; m < 16; m++) {
            float4 xv = *reinterpret_cast<const float4*>(&xs[m][4 * k4]);
            acc[m] = fmaf(xv.x, w0, acc[m]);
            acc[m] = fmaf(xv.y, w1, acc[m]);
            acc[m] = fmaf(xv.z, w2, acc[m]);
            acc[m] = fmaf(xv.w, w3, acc[m]);
        }
    }
    #pragma unroll
    for (int m = 0; m < 16; m++) g_facts[(r0 + m) * Fv + t] = acc[m];
}

// ---------------------------------------------------------------------------
// Kernel 2: fused main kernel. Block = 64 pair-rows x 256 cols, 256 threads.
// Thread tile: 16 rows x 4 cols.  Weights staged per 16-k chunk in smem,
// prefetched 2 chunks (~1000 cyc) ahead of use.
// ---------------------------------------------------------------------------
__global__ __launch_bounds__(256, 2) void ftlayer_main_kernel(
    const float* __restrict__ r_ij,
    const int* __restrict__ neighbors,
    const float* __restrict__ fw1, const float* __restrict__ fb1,
    const float* __restrict__ fw2, const float* __restrict__ fb2,
    const float* __restrict__ f2w, const float* __restrict__ f2b,
    float* __restrict__ out) {
    extern __shared__ float sm[];
    float* hT  = sm;                          // [256][HTS] transposed h, later y
    float* wb  = sm + Fv * HTS;               // [2][CBF] staged weight chunks
    float* r_s = wb + 2 * CBF;                // [TILE]
    int*   rjs = reinterpret_cast<int*>(r_s + TILE);  // [TILE]

    const int t   = threadIdx.x;
    const int rg  = t >> 6;                   // 0..3 row group
    const int cg  = t & 63;                   // 0..63 col group
    const int r0t = rg * 16;
    const int c0  = cg * 4;

    const int row0 = blockIdx.x * TILE;
    const int ba = row0 >> 7;                 // (b*A + a)
    const int bbase = (ba >> 9) << 9;         // b*A

    if (t < TILE) {
        int j = neighbors[row0 + t];
        j = min(max(j, 0), Av - 1);
        rjs[t] = bbase + j;
        r_s[t] = r_ij[row0 + t];
    }
    __syncthreads();

    // prologue: start loading weight chunks g=0,1 (fw2) while computing h
    float4 pfa[4], pfb[4];
    {
        const float4* s0 = reinterpret_cast<const float4*>(fw2);
        const float4* s1 = reinterpret_cast<const float4*>(fw2 + CBF);
        #pragma unroll
        for (int i = 0; i < 4; i++) pfa[i] = __ldg(s0 + t + i * 256);
        #pragma unroll
        for (int i = 0; i < 4; i++) pfb[i] = __ldg(s1 + t + i * 256);
    }

    // h transposed: thread t handles k=t for all 64 rows
    {
        const float w1v = fw1[t];
        const float b1v = fb1[t];
        float* hrow = hT + t * HTS;
        #pragma unroll 4
        for (int m = 0; m < TILE; m++)
            hrow[m] = sspf(fmaf(r_s[m], w1v, b1v));
    }
    // commit prologue chunks
    {
        float4* d0 = reinterpret_cast<float4*>(wb);
        float4* d1 = reinterpret_cast<float4*>(wb + CBF);
        #pragma unroll
        for (int i = 0; i < 4; i++) d0[t + i * 256] = pfa[i];
        #pragma unroll
        for (int i = 0; i < 4; i++) d1[t + i * 256] = pfb[i];
    }
    __syncthreads();

    unsigned long long acc[32];               // [c][q]: 4 cols x 8 row-pairs

    // =========================== GEMM1 =====================================
    {
        const float4 b4 = *reinterpret_cast<const float4*>(fb2 + c0);
        const float bb[4] = {b4.x, b4.y, b4.z, b4.w};
        #pragma unroll
        for (int c = 0; c < 4; c++) {
            const unsigned long long bp = pack2(bb[c], bb[c]);
            #pragma unroll
            for (int q = 0; q < 8; q++) acc[c * 8 + q] = bp;
        }
    }
    for (int c = 0; c < NCHUNK; c++) {
        // prefetch global chunk g = c+2 (fw2 tail, then f2w head)
        {
            const int g = c + 2;
            const float* src = (g < NCHUNK) ? (fw2 + g * CBF)
                                            : (f2w + (g - NCHUNK) * CBF);
            const float4* s4 = reinterpret_cast<const float4*>(src);
            #pragma unroll
            for (int i = 0; i < 4; i++) pfa[i] = __ldg(s4 + t + i * 256);
        }
        // compute 16 k-steps from wb[c&1]
        {
            const float* wchunk = wb + (c & 1) * CBF + c0;
            const float* hbase = hT + r0t + (c * CHUNK) * HTS;
            #pragma unroll
            for (int kk = 0; kk < CHUNK; kk++) {
                const float4 w4 =
                    *reinterpret_cast<const float4*>(wchunk + kk * Fv);
                const ulonglong2* hp =
                    reinterpret_cast<const ulonglong2*>(hbase + kk * HTS);
                ulonglong2 ha = hp[0], hb = hp[1], hc = hp[2], hd = hp[3];
                const unsigned long long h[8] = {ha.x, ha.y, hb.x, hb.y,
                                                 hc.x, hc.y, hd.x, hd.y};
                const float wv[4] = {w4.x, w4.y, w4.z, w4.w};
                #pragma unroll
                for (int cc = 0; cc < 4; cc++) {
                    const unsigned long long wd = pack2(wv[cc], wv[cc]);
                    #pragma unroll
                    for (int q = 0; q < 8; q++)
                        acc[cc * 8 + q] = fma2(h[q], wd, acc[cc * 8 + q]);
                }
            }
        }
        __syncthreads();   // all compute reads of wb[c&1] done
        {
            float4* d4 = reinterpret_cast<float4*>(wb + (c & 1) * CBF);
            #pragma unroll
            for (int i = 0; i < 4; i++) d4[t + i * 256] = pfa[i];
        }
        __syncthreads();   // staged chunk visible
    }

    // ---- epilogue 1: y = xi * W * xj, re-transpose into hT ----
    {
        const float4 xi4 = *reinterpret_cast<const float4*>(g_facts + ba * Fv + c0);
        const float xiv[4] = {xi4.x, xi4.y, xi4.z, xi4.w};
        #pragma unroll
        for (int q = 0; q < 8; q++) {
            const int ra = r0t + 2 * q, rb = ra + 1;
            const float4 xa = *reinterpret_cast<const float4*>(g_facts + rjs[ra] * Fv + c0);
            const float4 xb = *reinterpret_cast<const float4*>(g_facts + rjs[rb] * Fv + c0);
            const float xav[4] = {xa.x, xa.y, xa.z, xa.w};
            const float xbv[4] = {xb.x, xb.y, xb.z, xb.w};
            #pragma unroll
            for (int c = 0; c < 4; c++) {
                float2 s = unpack2(acc[c * 8 + q]);
                acc[c * 8 + q] = pack2(xiv[c] * s.x * xav[c],
                                       xiv[c] * s.y * xbv[c]);
            }
        }
    }
    // GEMM1 loop ended with __syncthreads: all hT reads done; safe to rewrite
    {
        #pragma unroll
        for (int c = 0; c < 4; c++) {
            unsigned long long* yrow =
                reinterpret_cast<unsigned long long*>(hT + (c0 + c) * HTS + r0t);
            #pragma unroll
            for (int q = 0; q < 8; q++) yrow[q] = acc[c * 8 + q];
        }
    }
    __syncthreads();

    // =========================== GEMM2 =====================================
    {
        const float4 b4 = *reinterpret_cast<const float4*>(f2b + c0);
        const float bb[4] = {b4.x, b4.y, b4.z, b4.w};
        #pragma unroll
        for (int c = 0; c < 4; c++) {
            const unsigned long long bp = pack2(bb[c], bb[c]);
            #pragma unroll
            for (int q = 0; q < 8; q++) acc[c * 8 + q] = bp;
        }
    }
    for (int c = 0; c < NCHUNK; c++) {
        if (c + 2 < NCHUNK) {   // prefetch f2w chunk c+2
            const float4* s4 =
                reinterpret_cast<const float4*>(f2w + (c + 2) * CBF);
            #pragma unroll
            for (int i = 0; i < 4; i++) pfa[i] = __ldg(s4 + t + i * 256);
        }
        {
            const float* wchunk = wb + (c & 1) * CBF + c0;
            const float* ybase = hT + r0t + (c * CHUNK) * HTS;
            #pragma unroll
            for (int kk = 0; kk < CHUNK; kk++) {
                const float4 w4 =
                    *reinterpret_cast<const float4*>(wchunk + kk * Fv);
                const ulonglong2* yp =
                    reinterpret_cast<const ulonglong2*>(ybase + kk * HTS);
                ulonglong2 ya = yp[0], yb = yp[1], yc = yp[2], yd = yp[3];
                const unsigned long long y[8] = {ya.x, ya.y, yb.x, yb.y,
                                                 yc.x, yc.y, yd.x, yd.y};
                const float wv[4] = {w4.x, w4.y, w4.z, w4.w};
                #pragma unroll
                for (int cc = 0; cc < 4; cc++) {
                    const unsigned long long wd = pack2(wv[cc], wv[cc]);
                    #pragma unroll
                    for (int q = 0; q < 8; q++)
                        acc[cc * 8 + q] = fma2(y[q], wd, acc[cc * 8 + q]);
                }
            }
        }
        if (c + 2 < NCHUNK) {
            __syncthreads();
            float4* d4 = reinterpret_cast<float4*>(wb + (c & 1) * CBF);
            #pragma unroll
            for (int i = 0; i < 4; i++) d4[t + i * 256] = pfa[i];
            __syncthreads();
        }
    }

    // ---- epilogue 2: ssp + coalesced float4 stores ----
    {
        float* ob = out + (long long)row0 * Fv + c0;
        #pragma unroll
        for (int q = 0; q < 8; q++) {
            const int ra = r0t + 2 * q, rb = ra + 1;
            float2 s0 = unpack2(acc[0 * 8 + q]);
            float2 s1 = unpack2(acc[1 * 8 + q]);
            float2 s2 = unpack2(acc[2 * 8 + q]);
            float2 s3 = unpack2(acc[3 * 8 + q]);
            float4 oa  = make_float4(sspf(s0.x), sspf(s1.x), sspf(s2.x), sspf(s3.x));
            float4 ob4 = make_float4(sspf(s0.y), sspf(s1.y), sspf(s2.y), sspf(s3.y));
            *reinterpret_cast<float4*>(ob + (long long)ra * Fv) = oa;
            *reinterpret_cast<float4*>(ob + (long long)rb * Fv) = ob4;
        }
    }
}

// ---------------------------------------------------------------------------
extern "C" void kernel_launch(void* const* d_in, const int* in_sizes, int n_in,
                              void* d_out, int out_size) {
    const float* x      = (const float*)d_in[0];
    const float* r_ij   = (const float*)d_in[1];
    // d_in[2] pairwise_mask: unused by reference
    const float* in2f_w = (const float*)d_in[3];
    const float* in2f_b = (const float*)d_in[4];
    const float* f2w    = (const float*)d_in[5];
    const float* f2b    = (const float*)d_in[6];
    const float* fw1    = (const float*)d_in[7];
    const float* fb1    = (const float*)d_in[8];
    const float* fw2    = (const float*)d_in[9];
    const float* fb2    = (const float*)d_in[10];
    const int*   nbr    = (const int*)d_in[11];   // int32 (JAX x64 disabled)
    float* out = (float*)d_out;

    const size_t smem_bytes =
        (size_t)(Fv * HTS + 2 * CBF + TILE) * sizeof(float) + TILE * sizeof(int);

    cudaFuncSetAttribute(ftlayer_main_kernel,
                         cudaFuncAttributeMaxDynamicSharedMemorySize,
                         (int)smem_bytes);

    facts_kernel<<<(Bv * Av) / 16, 256>>>(x, in2f_w, in2f_b);
    ftlayer_main_kernel<<<ROWS_TOTAL / TILE, 256, smem_bytes>>>(
        r_ij, nbr, fw1, fb1, fw2, fb2, f2w, f2b, out);
}

// round 16
// speedup vs baseline: 1.5169x; 1.1352x over previous
#include <cuda_runtime.h>
#include <cuda_bf16.h>
#include <cstdint>

// ---------------------------------------------------------------------------
// FTLayer via warp-level mma.sync (HMMA, bf16, fp32 accum) — compute_103-safe
// (no tcgen05 / no 'a'-suffix features; the harness PTX target lacks them).
//
// Both 256x256 GEMMs use a 3-pass bf16 split: A=hi+lo, B=hi+lo,
//   A@B ~= Ah@Bh + Al@Bh + Ah@Bl   (dropped lo*lo term ~2^-18)
// CTA = 64 pair-rows x 256 cols, 8 warps (2x4), warp tile 32x64.
// A (h, then y) in smem bf16 (stride 264 -> conflict-free frag LDS).
// B = pre-transposed weights wT[n][k] staged in 32-k double-buffered chunks
// (stride 40 -> conflict-free), each B_hi chunk reused for Ah and Al passes.
// neighbors = int32 (JAX x64 disabled).  Output: (B,A,128,256) f32
// ---------------------------------------------------------------------------

#define Bv 4
#define Av 512
#define Fv 256
#define ROWS_TOTAL (Bv * Av * 128)   // 262144 pair-rows
#define TILE 64                      // rows per CTA
#define AS 264                       // A smem row stride (bf16 elems), 528 B
#define BSTR 40                      // B chunk row stride (bf16 elems), 80 B
#define BCHUNK (256 * BSTR)          // bf16 elems per B buffer (20 KB)

// device scratch
__device__ float g_facts[Bv * Av * Fv];          // facts (B*A,256) fp32, L2-res
__device__ __nv_bfloat16 g_w2T_hi[Fv * Fv];      // fw2^T hi   [n][k]
__device__ __nv_bfloat16 g_w2T_lo[Fv * Fv];      // fw2^T lo
__device__ __nv_bfloat16 g_f2T_hi[Fv * Fv];      // f2w^T hi
__device__ __nv_bfloat16 g_f2T_lo[Fv * Fv];      // f2w^T lo

// shifted softplus: softplus(v) - ln2, matches jax.nn.softplus - LOG2
__device__ __forceinline__ float sspf(float v) {
    float a = fabsf(v);
    return fmaxf(v, 0.0f) + log1pf(__expf(-a)) - 0.6931471824645996f;
}

// split fp32 pair into bf16x2 hi word + bf16x2 lo word (elem0 in low half)
__device__ __forceinline__ void split2(float a, float b, uint32_t& hi,
                                       uint32_t& lo) {
    __nv_bfloat162 h = __floats2bfloat162_rn(a, b);
    float ra = a - __bfloat162float(h.x);
    float rb = b - __bfloat162float(h.y);
    __nv_bfloat162 l = __floats2bfloat162_rn(ra, rb);
    hi = *reinterpret_cast<uint32_t*>(&h);
    lo = *reinterpret_cast<uint32_t*>(&l);
}

// m16n8k16 row.col bf16 -> f32 accum (PTX ISA 7.0, compute_80+)
__device__ __forceinline__ void mma_bf16(float* d, const uint32_t* a,
                                         const uint32_t* b) {
    asm volatile(
        "mma.sync.aligned.m16n8k16.row.col.f32.bf16.bf16.f32 "
        "{%0,%1,%2,%3}, {%4,%5,%6,%7}, {%8,%9}, {%0,%1,%2,%3};"
        : "+f"(d[0]), "+f"(d[1]), "+f"(d[2]), "+f"(d[3])
        : "r"(a[0]), "r"(a[1]), "r"(a[2]), "r"(a[3]), "r"(b[0]), "r"(b[1]));
}

// ---------------------------------------------------------------------------
// prep: transpose + bf16-split both weight matrices: wT[n][k] = w[k][n]
// ---------------------------------------------------------------------------
__global__ __launch_bounds__(256) void prep_weights(
    const float* __restrict__ fw2, const float* __restrict__ f2w) {
    const int i = blockIdx.x * 256 + threadIdx.x;   // 65536
    const int n = i >> 8, k = i & 255;
    float w = fw2[k * Fv + n];
    __nv_bfloat16 h = __float2bfloat16(w);
    g_w2T_hi[n * Fv + k] = h;
    g_w2T_lo[n * Fv + k] = __float2bfloat16(w - __bfloat162float(h));
    float v = f2w[k * Fv + n];
    __nv_bfloat16 h2 = __float2bfloat16(v);
    g_f2T_hi[n * Fv + k] = h2;
    g_f2T_lo[n * Fv + k] = __float2bfloat16(v - __bfloat162float(h2));
}

// ---------------------------------------------------------------------------
// facts = x @ in2f_w + in2f_b  (fp32, exact)
// ---------------------------------------------------------------------------
__global__ __launch_bounds__(256) void facts_kernel(
    const float* __restrict__ x, const float* __restrict__ w,
    const float* __restrict__ b) {
    __shared__ float xs[16][Fv];
    const int t = threadIdx.x;
    const int r0 = blockIdx.x * 16;
    #pragma unroll
    for (int m = 0; m < 16; m++) xs[m][t] = x[(r0 + m) * Fv + t];
    __syncthreads();
    float acc[16];
    const float bias = b[t];
    #pragma unroll
    for (int m = 0; m < 16; m++) acc[m] = bias;
    for (int k4 = 0; k4 < Fv / 4; k4++) {
        const float w0 = w[(4 * k4 + 0) * Fv + t];
        const float w1 = w[(4 * k4 + 1) * Fv + t];
        const float w2 = w[(4 * k4 + 2) * Fv + t];
        const float w3 = w[(4 * k4 + 3) * Fv + t];
        #pragma unroll
        for (int m = 0; m < 16; m++) {
            float4 xv = *reinterpret_cast<const float4*>(&xs[m][4 * k4]);
            acc[m] = fmaf(xv.x, w0, acc[m]);
            acc[m] = fmaf(xv.y, w1, acc[m]);
            acc[m] = fmaf(xv.z, w2, acc[m]);
            acc[m] = fmaf(xv.w, w3, acc[m]);
        }
    }
    #pragma unroll
    for (int m = 0; m < 16; m++) g_facts[(r0 + m) * Fv + t] = acc[m];
}

// ---------------------------------------------------------------------------
// one 32-k chunk of MMAs.  DUAL: also accumulate A_lo x B (phase 1).
// acc layout: acc[mt*8+nt][4]
// ---------------------------------------------------------------------------
template <bool DUAL>
__device__ __forceinline__ void chunk_mma(
    const __nv_bfloat16* __restrict__ Ah, const __nv_bfloat16* __restrict__ Al,
    const __nv_bfloat16* __restrict__ Bbuf, float (*acc)[4], int kc, int g,
    int t2, int wm, int wn) {
    #pragma unroll
    for (int s = 0; s < 2; s++) {
        const int kk = kc + s * 16;
        uint32_t bf[8][2];
        #pragma unroll
        for (int nt = 0; nt < 8; nt++) {
            const __nv_bfloat16* bp =
                Bbuf + (wn * 64 + nt * 8 + g) * BSTR + s * 16 + t2;
            bf[nt][0] = *reinterpret_cast<const uint32_t*>(bp);
            bf[nt][1] = *reinterpret_cast<const uint32_t*>(bp + 8);
        }
        #pragma unroll
        for (int mt = 0; mt < 2; mt++) {
            const int r = wm * 32 + mt * 16 + g;
            const __nv_bfloat16* ap = Ah + r * AS + kk + t2;
            uint32_t ah[4];
            ah[0] = *reinterpret_cast<const uint32_t*>(ap);
            ah[1] = *reinterpret_cast<const uint32_t*>(ap + 8 * AS);
            ah[2] = *reinterpret_cast<const uint32_t*>(ap + 8);
            ah[3] = *reinterpret_cast<const uint32_t*>(ap + 8 * AS + 8);
            #pragma unroll
            for (int nt = 0; nt < 8; nt++) mma_bf16(acc[mt * 8 + nt], ah, bf[nt]);
            if (DUAL) {
                const __nv_bfloat16* lp = Al + r * AS + kk + t2;
                uint32_t al[4];
                al[0] = *reinterpret_cast<const uint32_t*>(lp);
                al[1] = *reinterpret_cast<const uint32_t*>(lp + 8 * AS);
                al[2] = *reinterpret_cast<const uint32_t*>(lp + 8);
                al[3] = *reinterpret_cast<const uint32_t*>(lp + 8 * AS + 8);
                #pragma unroll
                for (int nt = 0; nt < 8; nt++)
                    mma_bf16(acc[mt * 8 + nt], al, bf[nt]);
            }
        }
    }
}

// ---------------------------------------------------------------------------
// full K=256 x {3 bf16 passes} GEMM: 16 staged chunks (8 B_hi dual + 8 B_lo).
// caller must have committed chunk 0 (from Whi) into buffer 0.
// ---------------------------------------------------------------------------
__device__ __forceinline__ void run_gemm(
    const __nv_bfloat16* __restrict__ Ah, const __nv_bfloat16* __restrict__ Al,
    __nv_bfloat16* Bb, const __nv_bfloat16* __restrict__ Whi,
    const __nv_bfloat16* __restrict__ Wlo, float (*acc)[4], int t, int g,
    int t2, int wm, int wn) {
    uint4 pf[4];
    #pragma unroll 1
    for (int i = 0; i < 16; i++) {
        if (i < 15) {                 // prefetch chunk i+1 (row t, 64 B)
            const int j = i + 1;
            const uint4* s4 = reinterpret_cast<const uint4*>(
                (j < 8 ? Whi : Wlo) + t * Fv + (j & 7) * 32);
            #pragma unroll
            for (int q = 0; q < 4; q++) pf[q] = __ldg(s4 + q);
        }
        const __nv_bfloat16* Bbuf = Bb + (i & 1) * BCHUNK;
        if (i < 8)
            chunk_mma<true>(Ah, Al, Bbuf, acc, (i & 7) * 32, g, t2, wm, wn);
        else
            chunk_mma<false>(Ah, Al, Bbuf, acc, (i & 7) * 32, g, t2, wm, wn);
        __syncthreads();
        if (i < 15) {
            uint4* d4 =
                reinterpret_cast<uint4*>(Bb + ((i + 1) & 1) * BCHUNK + t * BSTR);
            #pragma unroll
            for (int q = 0; q < 4; q++) d4[q] = pf[q];
        }
        __syncthreads();
    }
}

// ---------------------------------------------------------------------------
// main kernel
// ---------------------------------------------------------------------------
__global__ __launch_bounds__(256, 2) void ft_main(
    const float* __restrict__ r_ij, const int* __restrict__ nbr,
    const float* __restrict__ fw1, const float* __restrict__ fb1,
    const float* __restrict__ fb2, const float* __restrict__ f2b,
    float* __restrict__ out) {
    extern __shared__ __nv_bfloat16 smem[];
    __nv_bfloat16* Ah = smem;                    // [64][AS]
    __nv_bfloat16* Al = Ah + TILE * AS;          // [64][AS]
    __nv_bfloat16* Bb = Al + TILE * AS;          // [2][BCHUNK]
    __shared__ float r_s[TILE];
    __shared__ int rjs[TILE];

    const int t = threadIdx.x;
    const int lane = t & 31, w = t >> 5;
    const int g = lane >> 2, t2 = (lane & 3) * 2;
    const int wm = w & 1, wn = w >> 1;           // warp grid 2(M) x 4(N)

    const int row0 = blockIdx.x * TILE;
    const int ba = row0 >> 7;                    // (b*A + a)
    const int bbase = (ba >> 9) << 9;            // b*A

    if (t < TILE) {
        int j = nbr[row0 + t];
        rjs[t] = bbase + min(max(j, 0), Av - 1);
        r_s[t] = r_ij[row0 + t];
    }
    // prefetch fw2^T hi chunk 0
    uint4 pf[4];
    {
        const uint4* s4 = reinterpret_cast<const uint4*>(g_w2T_hi + t * Fv);
        #pragma unroll
        for (int q = 0; q < 4; q++) pf[q] = __ldg(s4 + q);
    }
    __syncthreads();

    // h[m][k] = ssp(r_m * fw1_k + fb1_k), split into Ah/Al
    {
        const int m = t >> 2, kq = (t & 3) * 64;
        const float rv = r_s[m];
        #pragma unroll 4
        for (int i = 0; i < 64; i += 2) {
            const int k = kq + i;
            float f0 = sspf(fmaf(rv, __ldg(fw1 + k), __ldg(fb1 + k)));
            float f1 = sspf(fmaf(rv, __ldg(fw1 + k + 1), __ldg(fb1 + k + 1)));
            uint32_t hi, lo;
            split2(f0, f1, hi, lo);
            *reinterpret_cast<uint32_t*>(Ah + m * AS + k) = hi;
            *reinterpret_cast<uint32_t*>(Al + m * AS + k) = lo;
        }
    }
    // commit B chunk 0 into buffer 0
    {
        uint4* d4 = reinterpret_cast<uint4*>(Bb + t * BSTR);
        #pragma unroll
        for (int q = 0; q < 4; q++) d4[q] = pf[q];
    }
    __syncthreads();

    float acc[16][4];
    #pragma unroll
    for (int i = 0; i < 16; i++)
        #pragma unroll
        for (int q = 0; q < 4; q++) acc[i][q] = 0.0f;

    // ---- GEMM1: W = h @ fw2 (3-pass split) ----
    run_gemm(Ah, Al, Bb, g_w2T_hi, g_w2T_lo, acc, t, g, t2, wm, wn);

    // prefetch f2w^T hi chunk 0
    {
        const uint4* s4 = reinterpret_cast<const uint4*>(g_f2T_hi + t * Fv);
        #pragma unroll
        for (int q = 0; q < 4; q++) pf[q] = __ldg(s4 + q);
    }
    // ---- epilogue 1: y = xi*(W+fb2)*xj, split into Ah/Al ----
    {
        const float* xib = g_facts + (size_t)ba * Fv;
        #pragma unroll
        for (int mt = 0; mt < 2; mt++) {
            const int r1 = wm * 32 + mt * 16 + g, r2 = r1 + 8;
            const float* xj1 = g_facts + (size_t)rjs[r1] * Fv;
            const float* xj2 = g_facts + (size_t)rjs[r2] * Fv;
            #pragma unroll
            for (int nt = 0; nt < 8; nt++) {
                const int col = wn * 64 + nt * 8 + t2;
                const float2 xi = *reinterpret_cast<const float2*>(xib + col);
                const float2 bb = *reinterpret_cast<const float2*>(fb2 + col);
                const float2 a1 = *reinterpret_cast<const float2*>(xj1 + col);
                const float2 a2 = *reinterpret_cast<const float2*>(xj2 + col);
                float* d = acc[mt * 8 + nt];
                float y0 = xi.x * (d[0] + bb.x) * a1.x;
                float y1 = xi.y * (d[1] + bb.y) * a1.y;
                float y2 = xi.x * (d[2] + bb.x) * a2.x;
                float y3 = xi.y * (d[3] + bb.y) * a2.y;
                uint32_t hi, lo;
                split2(y0, y1, hi, lo);
                *reinterpret_cast<uint32_t*>(Ah + r1 * AS + col) = hi;
                *reinterpret_cast<uint32_t*>(Al + r1 * AS + col) = lo;
                split2(y2, y3, hi, lo);
                *reinterpret_cast<uint32_t*>(Ah + r2 * AS + col) = hi;
                *reinterpret_cast<uint32_t*>(Al + r2 * AS + col) = lo;
            }
        }
    }
    __syncthreads();        // A rewritten by all warps; buffer 0 free
    {
        uint4* d4 = reinterpret_cast<uint4*>(Bb + t * BSTR);
        #pragma unroll
        for (int q = 0; q < 4; q++) d4[q] = pf[q];
    }
    #pragma unroll
    for (int i = 0; i < 16; i++)
        #pragma unroll
        for (int q = 0; q < 4; q++) acc[i][q] = 0.0f;
    __syncthreads();

    // ---- GEMM2: out = y @ f2w (3-pass split) ----
    run_gemm(Ah, Al, Bb, g_f2T_hi, g_f2T_lo, acc, t, g, t2, wm, wn);

    // ---- epilogue 2: out = ssp(D + f2b), float2 stores ----
    {
        #pragma unroll
        for (int mt = 0; mt < 2; mt++) {
            const int r1 = wm * 32 + mt * 16 + g, r2 = r1 + 8;
            float* o1 = out + (size_t)(row0 + r1) * Fv;
            float* o2 = out + (size_t)(row0 + r2) * Fv;
            #pragma unroll
            for (int nt = 0; nt < 8; nt++) {
                const int col = wn * 64 + nt * 8 + t2;
                const float2 bb = *reinterpret_cast<const float2*>(f2b + col);
                float* d = acc[mt * 8 + nt];
                float2 v1, v2;
                v1.x = sspf(d[0] + bb.x);
                v1.y = sspf(d[1] + bb.y);
                v2.x = sspf(d[2] + bb.x);
                v2.y = sspf(d[3] + bb.y);
                *reinterpret_cast<float2*>(o1 + col) = v1;
                *reinterpret_cast<float2*>(o2 + col) = v2;
            }
        }
    }
}

// ---------------------------------------------------------------------------
extern "C" void kernel_launch(void* const* d_in, const int* in_sizes, int n_in,
                              void* d_out, int out_size) {
    const float* x      = (const float*)d_in[0];
    const float* r_ij   = (const float*)d_in[1];
    // d_in[2] pairwise_mask: unused by reference
    const float* in2f_w = (const float*)d_in[3];
    const float* in2f_b = (const float*)d_in[4];
    const float* f2w    = (const float*)d_in[5];
    const float* f2b    = (const float*)d_in[6];
    const float* fw1    = (const float*)d_in[7];
    const float* fb1    = (const float*)d_in[8];
    const float* fw2    = (const float*)d_in[9];
    const float* fb2    = (const float*)d_in[10];
    const int*   nbr    = (const int*)d_in[11];   // int32 (JAX x64 disabled)
    float* out = (float*)d_out;

    const int smem_bytes = (2 * TILE * AS + 2 * BCHUNK) * 2;   // 108544 B
    cudaFuncSetAttribute(ft_main, cudaFuncAttributeMaxDynamicSharedMemorySize,
                         smem_bytes);

    prep_weights<<<(Fv * Fv) / 256, 256>>>(fw2, f2w);
    facts_kernel<<<(Bv * Av) / 16, 256>>>(x, in2f_w, in2f_b);
    ft_main<<<ROWS_TOTAL / TILE, 256, smem_bytes>>>(r_ij, nbr, fw1, fb1, fb2,
                                                    f2b, out);
}